// round 1
// baseline (speedup 1.0000x reference)
#include <cuda_runtime.h>
#include <cuda_bf16.h>

// Shapes (compile-time; problem is fixed-shape)
#define B_   2
#define N_   1024
#define D_   256
#define E_   64
#define H_   8
#define HS_  64
#define FF_  1024
#define R_   (B_*N_)        // 2048 token rows
#define QKV_ (3*H_*HS_)     // 1536

// ---------------------------------------------------------------------------
// Scratch (device globals; no runtime allocation allowed)
// ---------------------------------------------------------------------------
__device__ float g_qkv[R_*QKV_];                    // q | kn | v   (12 MB)
__device__ float g_qe[R_*H_*E_];                    // 4 MB
__device__ float g_logits[(long)B_*H_*N_*N_];       // 64 MB (reused as attn probs)
__device__ float g_mo[R_*H_*HS_];                   // 4 MB
__device__ float g_mha[R_*D_];                      // 2 MB
__device__ float g_x[R_*D_];                        // 2 MB
__device__ float g_ffh[R_*FF_];                     // 8 MB
__device__ float g_ff[R_*D_];                       // 2 MB
__device__ float g_wqkv[D_*QKV_];                   // 1.5 MB

// ---------------------------------------------------------------------------
// Repack Wq (scaled by 1/sqrt(HS)), Wk[:, :D], Wv into [256, 1536]
// ---------------------------------------------------------------------------
__global__ void repack_wqkv(const float* __restrict__ Wq,
                            const float* __restrict__ Wk,
                            const float* __restrict__ Wv,
                            float* __restrict__ out)
{
    int idx = blockIdx.x * blockDim.x + threadIdx.x;
    if (idx >= D_ * QKV_) return;
    int i = idx / QKV_;
    int j = idx % QKV_;
    float v;
    if (j < 512) {
        int h = j >> 6, o = j & 63;
        v = Wq[(h*D_ + i)*HS_ + o] * 0.125f;               // 1/sqrt(64)
    } else if (j < 1024) {
        int jj = j - 512; int h = jj >> 6, o = jj & 63;
        v = Wk[(h*(D_+E_) + i)*HS_ + o];
    } else {
        int jj = j - 1024; int h = jj >> 6, o = jj & 63;
        v = Wv[(h*D_ + i)*HS_ + o];
    }
    out[idx] = v;
}

// ---------------------------------------------------------------------------
// Generic strided / batched SGEMM.
//   C[m,n] = sum_k A[m,k] * B[k,n]   (+bias, +relu per epi)
// A element at A + m*as_m + k  (K contiguous in A, always true here)
// B element at B + k*bs_k + n*bs_n  (either bs_n==1 or bs_k==1)
// Batch z: bo = z/inner, bi = z%inner; per-operand (bso, bsi) offsets.
// All M,N,K are exact multiples of the tile sizes for every call below.
// ---------------------------------------------------------------------------
template<int BM, int BN, int BK, int TM, int TN, int NT>
__global__ __launch_bounds__(NT)
void sgemm_kernel(const float* __restrict__ A, const float* __restrict__ Bm,
                  const float* __restrict__ bias, float* __restrict__ C,
                  int K,
                  long as_m, long a_bso, long a_bsi,
                  long bs_k, long bs_n, long b_bso, long b_bsi,
                  long cs_m, long c_bso, long c_bsi,
                  int inner, int epi)
{
    __shared__ float As[BK][BM + 4];
    __shared__ float Bs[BK][BN + 4];

    const int t  = threadIdx.x;
    const int TX = BN / TN;
    const int tx = t % TX;
    const int ty = t / TX;
    const long bo = blockIdx.z / inner;
    const long bi = blockIdx.z % inner;
    const long m0 = (long)blockIdx.y * BM;
    const long n0 = (long)blockIdx.x * BN;

    const float* Ab = A  + bo*a_bso + bi*a_bsi + m0*as_m;
    const float* Bb = Bm + bo*b_bso + bi*b_bsi + n0*bs_n;

    float acc[TM][TN];
#pragma unroll
    for (int i = 0; i < TM; ++i)
#pragma unroll
        for (int j = 0; j < TN; ++j) acc[i][j] = 0.f;

    for (int k0 = 0; k0 < K; k0 += BK) {
        // ---- load A tile (BM x BK), K contiguous ----
#pragma unroll
        for (int i = 0; i < (BM*BK/4)/NT; ++i) {
            int f   = t + i*NT;
            int row = f / (BK/4);
            int c4  = f % (BK/4);
            float4 v = *(const float4*)(Ab + (long)row*as_m + k0 + c4*4);
            As[c4*4+0][row] = v.x;
            As[c4*4+1][row] = v.y;
            As[c4*4+2][row] = v.z;
            As[c4*4+3][row] = v.w;
        }
        // ---- load B tile (BK x BN) ----
        if (bs_n == 1) {
#pragma unroll
            for (int i = 0; i < (BK*BN/4)/NT; ++i) {
                int f  = t + i*NT;
                int k  = f / (BN/4);
                int n4 = f % (BN/4);
                float4 v = *(const float4*)(Bb + (long)(k0+k)*bs_k + n4*4);
                *(float4*)&Bs[k][n4*4] = v;
            }
        } else {   // bs_k == 1 (K contiguous in B)
#pragma unroll
            for (int i = 0; i < (BK*BN/4)/NT; ++i) {
                int f  = t + i*NT;
                int n  = f / (BK/4);
                int c4 = f % (BK/4);
                float4 v = *(const float4*)(Bb + (long)n*bs_n + k0 + c4*4);
                Bs[c4*4+0][n] = v.x;
                Bs[c4*4+1][n] = v.y;
                Bs[c4*4+2][n] = v.z;
                Bs[c4*4+3][n] = v.w;
            }
        }
        __syncthreads();

#pragma unroll
        for (int kk = 0; kk < BK; ++kk) {
            float a[TM], b[TN];
#pragma unroll
            for (int g = 0; g < TM/4; ++g) {
                const float4 v = *(const float4*)&As[kk][(g ? BM/2 : 0) + ty*4];
                a[g*4+0] = v.x; a[g*4+1] = v.y; a[g*4+2] = v.z; a[g*4+3] = v.w;
            }
#pragma unroll
            for (int g = 0; g < TN/4; ++g) {
                const float4 v = *(const float4*)&Bs[kk][(g ? BN/2 : 0) + tx*4];
                b[g*4+0] = v.x; b[g*4+1] = v.y; b[g*4+2] = v.z; b[g*4+3] = v.w;
            }
#pragma unroll
            for (int i = 0; i < TM; ++i)
#pragma unroll
                for (int j = 0; j < TN; ++j)
                    acc[i][j] = fmaf(a[i], b[j], acc[i][j]);
        }
        __syncthreads();
    }

    float* Cb = C + bo*c_bso + bi*c_bsi;
#pragma unroll
    for (int gm = 0; gm < TM/4; ++gm) {
#pragma unroll
        for (int u = 0; u < 4; ++u) {
            const long row = m0 + (gm ? BM/2 : 0) + ty*4 + u;
#pragma unroll
            for (int gn = 0; gn < TN/4; ++gn) {
                const long col = n0 + (gn ? BN/2 : 0) + tx*4;
                float4 v;
                v.x = acc[gm*4+u][gn*4+0];
                v.y = acc[gm*4+u][gn*4+1];
                v.z = acc[gm*4+u][gn*4+2];
                v.w = acc[gm*4+u][gn*4+3];
                if (epi) {
                    const float4 bv = *(const float4*)(bias + col);
                    v.x += bv.x; v.y += bv.y; v.z += bv.z; v.w += bv.w;
                    if (epi == 2) {
                        v.x = fmaxf(v.x, 0.f); v.y = fmaxf(v.y, 0.f);
                        v.z = fmaxf(v.z, 0.f); v.w = fmaxf(v.w, 0.f);
                    }
                }
                *(float4*)(Cb + row*cs_m + col) = v;
            }
        }
    }
}

// ---------------------------------------------------------------------------
// Edge-conditioned logits + softmax, fused. One CTA per (b, n).
//   logits[b,h,n,m] += sum_e qe[b,n,h,e] * edge[b,n,m,e]  ; softmax over m.
// Streams 536 MB of edge exactly once (DRAM-bound). 128 threads.
// smem: logits[8][1024] | edge tile [256][17 float4] (padded) | qe [8][16 f4]
// ---------------------------------------------------------------------------
#define EDGE_SMEM_BYTES ((8192 + 256*17*4 + 128*4) * 4)   // 104448

__global__ __launch_bounds__(128)
void edge_softmax_kernel(const float* __restrict__ edge,
                         const float* __restrict__ qe,
                         float* __restrict__ logits)
{
    extern __shared__ float smem[];
    float*  s_logits = smem;                       // 8192 floats
    float4* s_edge4  = (float4*)(smem + 8192);     // 256*17 float4
    float4* s_qe4    = s_edge4 + 256*17;           // 128 float4

    const int t  = threadIdx.x;
    const int bn = blockIdx.x;
    const int b  = bn >> 10;
    const int n  = bn & 1023;

    // qe row: 512 floats
    s_qe4[t] = ((const float4*)(qe + (long)bn*512))[t];

    // init s_logits with QK logits
    const float* lg = logits + ((long)(b*H_)*N_ + n) * N_;
#pragma unroll
    for (int h = 0; h < H_; ++h) {
        const float4* src = (const float4*)(lg + (long)h*N_*N_);
        float4* dst = (float4*)(s_logits + h*N_);
        dst[t]       = src[t];
        dst[t + 128] = src[t + 128];
    }
    __syncthreads();

    const float4* eg = (const float4*)(edge + ((long)bn << 16));
    const int tx = t & 63;            // m lane
    const int hy = (t >> 6) << 2;     // head group base: 0 or 4

    for (int mt = 0; mt < 4; ++mt) {
        // load edge tile rows [mt*256, mt*256+256)
#pragma unroll 8
        for (int i = 0; i < 32; ++i) {
            int f   = t + i*128;
            int row = f >> 4, c = f & 15;
            s_edge4[row*17 + c] = eg[(mt*256 + row)*16 + c];
        }
        __syncthreads();

        float acc[4][4];
#pragma unroll
        for (int i = 0; i < 4; ++i)
#pragma unroll
            for (int j = 0; j < 4; ++j) acc[i][j] = 0.f;

#pragma unroll
        for (int e4 = 0; e4 < 16; ++e4) {
            float4 ev[4], qv[4];
#pragma unroll
            for (int i = 0; i < 4; ++i) ev[i] = s_edge4[(tx + i*64)*17 + e4];
#pragma unroll
            for (int j = 0; j < 4; ++j) qv[j] = s_qe4[(hy + j)*16 + e4];
#pragma unroll
            for (int i = 0; i < 4; ++i)
#pragma unroll
                for (int j = 0; j < 4; ++j)
                    acc[i][j] += ev[i].x*qv[j].x + ev[i].y*qv[j].y
                               + ev[i].z*qv[j].z + ev[i].w*qv[j].w;
        }
#pragma unroll
        for (int j = 0; j < 4; ++j)
#pragma unroll
            for (int i = 0; i < 4; ++i)
                s_logits[(hy + j)*N_ + mt*256 + i*64 + tx] += acc[i][j];
        __syncthreads();
    }

    // softmax per head (4 warps x 2 heads), write probs over logits in-place
    const int warp = t >> 5, lane = t & 31;
    for (int h = warp; h < H_; h += 4) {
        const float* row = s_logits + h*N_;
        float mx = -1e30f;
#pragma unroll
        for (int i = 0; i < 32; ++i) mx = fmaxf(mx, row[lane + i*32]);
#pragma unroll
        for (int o = 16; o; o >>= 1) mx = fmaxf(mx, __shfl_xor_sync(~0u, mx, o));
        float vals[32];
        float sum = 0.f;
#pragma unroll
        for (int i = 0; i < 32; ++i) {
            vals[i] = __expf(row[lane + i*32] - mx);
            sum += vals[i];
        }
#pragma unroll
        for (int o = 16; o; o >>= 1) sum += __shfl_xor_sync(~0u, sum, o);
        const float inv = 1.f / sum;
        float* out = logits + ((long)(b*H_ + h)*N_ + n) * N_;
#pragma unroll
        for (int i = 0; i < 32; ++i) out[lane + i*32] = vals[i] * inv;
    }
}

// ---------------------------------------------------------------------------
// LayerNorm over last dim (256) with fused residual add. Warp per row.
// out = (a + r - mu) * rsqrt(var + eps) * g + beta
// ---------------------------------------------------------------------------
__global__ __launch_bounds__(256)
void ln_kernel(const float* __restrict__ a, const float* __restrict__ r,
               const float* __restrict__ gam, const float* __restrict__ bet,
               float* __restrict__ out)
{
    const int warp = threadIdx.x >> 5, lane = threadIdx.x & 31;
    const long row = (long)blockIdx.x * 8 + warp;
    const float4* pa = (const float4*)(a + row*D_);
    const float4* pr = (const float4*)(r + row*D_);
    float4 v0 = pa[lane], v1 = pa[lane + 32];
    const float4 q0 = pr[lane], q1 = pr[lane + 32];
    v0.x += q0.x; v0.y += q0.y; v0.z += q0.z; v0.w += q0.w;
    v1.x += q1.x; v1.y += q1.y; v1.z += q1.z; v1.w += q1.w;

    float s = v0.x + v0.y + v0.z + v0.w + v1.x + v1.y + v1.z + v1.w;
#pragma unroll
    for (int o = 16; o; o >>= 1) s += __shfl_xor_sync(~0u, s, o);
    const float mu = s * (1.f / 256.f);

    float4 d0, d1;
    d0.x = v0.x - mu; d0.y = v0.y - mu; d0.z = v0.z - mu; d0.w = v0.w - mu;
    d1.x = v1.x - mu; d1.y = v1.y - mu; d1.z = v1.z - mu; d1.w = v1.w - mu;
    float var = d0.x*d0.x + d0.y*d0.y + d0.z*d0.z + d0.w*d0.w
              + d1.x*d1.x + d1.y*d1.y + d1.z*d1.z + d1.w*d1.w;
#pragma unroll
    for (int o = 16; o; o >>= 1) var += __shfl_xor_sync(~0u, var, o);
    const float rs = rsqrtf(var * (1.f / 256.f) + 1e-6f);

    const float4 g0 = ((const float4*)gam)[lane], g1 = ((const float4*)gam)[lane + 32];
    const float4 b0 = ((const float4*)bet)[lane], b1 = ((const float4*)bet)[lane + 32];
    float4 o0, o1;
    o0.x = d0.x*rs*g0.x + b0.x; o0.y = d0.y*rs*g0.y + b0.y;
    o0.z = d0.z*rs*g0.z + b0.z; o0.w = d0.w*rs*g0.w + b0.w;
    o1.x = d1.x*rs*g1.x + b1.x; o1.y = d1.y*rs*g1.y + b1.y;
    o1.z = d1.z*rs*g1.z + b1.z; o1.w = d1.w*rs*g1.w + b1.w;
    ((float4*)(out + row*D_))[lane]      = o0;
    ((float4*)(out + row*D_))[lane + 32] = o1;
}

// ---------------------------------------------------------------------------
// Host launch (graph-capturable: kernel launches + attribute/symbol queries)
// ---------------------------------------------------------------------------
extern "C" void kernel_launch(void* const* d_in, const int* in_sizes, int n_in,
                              void* d_out, int out_size)
{
    const float* node = (const float*)d_in[0];
    const float* edge = (const float*)d_in[1];
    const float* Wq   = (const float*)d_in[2];
    const float* Wk   = (const float*)d_in[3];
    const float* Wv   = (const float*)d_in[4];
    const float* Wp   = (const float*)d_in[5];
    const float* bp   = (const float*)d_in[6];
    const float* ln1g = (const float*)d_in[7];
    const float* ln1b = (const float*)d_in[8];
    const float* W1   = (const float*)d_in[9];
    const float* b1   = (const float*)d_in[10];
    const float* W2   = (const float*)d_in[11];
    const float* b2   = (const float*)d_in[12];
    const float* ln2g = (const float*)d_in[13];
    const float* ln2b = (const float*)d_in[14];

    float *qkv, *qe, *logits, *mo, *mha, *x, *ffh, *ff, *wqkv;
    cudaGetSymbolAddress((void**)&qkv,    g_qkv);
    cudaGetSymbolAddress((void**)&qe,     g_qe);
    cudaGetSymbolAddress((void**)&logits, g_logits);
    cudaGetSymbolAddress((void**)&mo,     g_mo);
    cudaGetSymbolAddress((void**)&mha,    g_mha);
    cudaGetSymbolAddress((void**)&x,      g_x);
    cudaGetSymbolAddress((void**)&ffh,    g_ffh);
    cudaGetSymbolAddress((void**)&ff,     g_ff);
    cudaGetSymbolAddress((void**)&wqkv,   g_wqkv);

    cudaFuncSetAttribute(edge_softmax_kernel,
                         cudaFuncAttributeMaxDynamicSharedMemorySize,
                         EDGE_SMEM_BYTES);

    // 0) weight repack
    repack_wqkv<<<(D_*QKV_ + 255)/256, 256>>>(Wq, Wk, Wv, wqkv);

    // 1) fused QKV projection: [2048,1536] = node[2048,256] @ wqkv[256,1536]
    sgemm_kernel<128,128,16,8,8,256><<<dim3(QKV_/128, R_/128, 1), 256>>>(
        node, wqkv, nullptr, qkv, D_,
        /*as_m*/D_, 0, 0,
        /*bs_k*/QKV_, /*bs_n*/1, 0, 0,
        /*cs_m*/QKV_, 0, 0, 1, 0);

    // 2) qe[r, h*64+e] = q_h[r,:] @ WkE_h^T  (batch over h)
    sgemm_kernel<128,64,16,8,8,128><<<dim3(1, R_/128, H_), 128>>>(
        qkv, Wk + (long)D_*HS_, nullptr, qe, HS_,
        /*as_m*/QKV_, /*a_bso*/64, 0,
        /*bs_k*/1, /*bs_n*/HS_, /*b_bso*/(long)(D_+E_)*HS_, 0,
        /*cs_m*/H_*E_, /*c_bso*/64, 0, 1, 0);

    // 3) QK^T logits: batch over (b,h); C[n,m] = q . kn
    sgemm_kernel<128,128,16,8,8,256><<<dim3(N_/128, N_/128, B_*H_), 256>>>(
        qkv, qkv + 512, nullptr, logits, HS_,
        /*as_m*/QKV_, /*a_bso*/(long)N_*QKV_, /*a_bsi*/64,
        /*bs_k*/1, /*bs_n*/QKV_, /*b_bso*/(long)N_*QKV_, /*b_bsi*/64,
        /*cs_m*/N_, /*c_bso*/(long)H_*N_*N_, /*c_bsi*/(long)N_*N_,
        /*inner*/H_, 0);

    // 4) edge logits + softmax (streams 536 MB; in-place probs)
    edge_softmax_kernel<<<R_, 128, EDGE_SMEM_BYTES>>>(edge, qe, logits);

    // 5) AV: mo[b,n,h,:] = attn[b,h,n,:] @ v[b,:,h,:]
    sgemm_kernel<128,64,16,8,8,128><<<dim3(1, N_/128, B_*H_), 128>>>(
        logits, qkv + 1024, nullptr, mo, N_,
        /*as_m*/N_, /*a_bso*/(long)H_*N_*N_, /*a_bsi*/(long)N_*N_,
        /*bs_k*/QKV_, /*bs_n*/1, /*b_bso*/(long)N_*QKV_, /*b_bsi*/64,
        /*cs_m*/H_*HS_, /*c_bso*/(long)N_*H_*HS_, /*c_bsi*/64,
        /*inner*/H_, 0);

    // 6) output projection: mha = mo[2048,512] @ Wp[512,256] + bp
    sgemm_kernel<128,64,16,8,8,128><<<dim3(D_/64, R_/128, 1), 128>>>(
        mo, Wp, bp, mha, H_*HS_,
        /*as_m*/H_*HS_, 0, 0,
        /*bs_k*/D_, /*bs_n*/1, 0, 0,
        /*cs_m*/D_, 0, 0, 1, 1);

    // 7) x = LN1(node + mha)
    ln_kernel<<<R_/8, 256>>>(node, mha, ln1g, ln1b, x);

    // 8) FFN hidden: ffh = relu(x @ W1 + b1)
    sgemm_kernel<128,128,16,8,8,256><<<dim3(FF_/128, R_/128, 1), 256>>>(
        x, W1, b1, ffh, D_,
        /*as_m*/D_, 0, 0,
        /*bs_k*/FF_, /*bs_n*/1, 0, 0,
        /*cs_m*/FF_, 0, 0, 1, 2);

    // 9) FFN out: ff = ffh @ W2 + b2
    sgemm_kernel<64,64,16,4,8,128><<<dim3(D_/64, R_/64, 1), 128>>>(
        ffh, W2, b2, ff, FF_,
        /*as_m*/FF_, 0, 0,
        /*bs_k*/D_, /*bs_n*/1, 0, 0,
        /*cs_m*/D_, 0, 0, 1, 1);

    // 10) out = LN2(x + ff)
    ln_kernel<<<R_/8, 256>>>(x, ff, ln2g, ln2b, (float*)d_out);
}

// round 2
// speedup vs baseline: 1.3393x; 1.3393x over previous
#include <cuda_runtime.h>
#include <cuda_bf16.h>
#include <mma.h>

using namespace nvcuda;

// Shapes (compile-time; problem is fixed-shape)
#define B_   2
#define N_   1024
#define D_   256
#define E_   64
#define H_   8
#define HS_  64
#define FF_  1024
#define R_   (B_*N_)        // 2048 token rows
#define QKV_ (3*H_*HS_)     // 1536

// ---------------------------------------------------------------------------
// Scratch (device globals; no runtime allocation allowed)
// ---------------------------------------------------------------------------
__device__ float g_qkv[R_*QKV_];                    // q | kn | v   (12 MB)
__device__ float g_qe[R_*H_*E_];                    // 4 MB
__device__ float g_logits[(long)B_*H_*N_*N_];       // 64 MB (reused as attn probs)
__device__ float g_mo[R_*H_*HS_];                   // 4 MB
__device__ float g_mha[R_*D_];                      // 2 MB
__device__ float g_x[R_*D_];                        // 2 MB
__device__ float g_ffh[R_*FF_];                     // 8 MB
__device__ float g_ff[R_*D_];                       // 2 MB
__device__ float g_wqkv[D_*QKV_];                   // 1.5 MB

// ---------------------------------------------------------------------------
// Repack Wq (scaled by 1/sqrt(HS)), Wk[:, :D], Wv into [256, 1536]
// ---------------------------------------------------------------------------
__global__ void repack_wqkv(const float* __restrict__ Wq,
                            const float* __restrict__ Wk,
                            const float* __restrict__ Wv,
                            float* __restrict__ out)
{
    int idx = blockIdx.x * blockDim.x + threadIdx.x;
    if (idx >= D_ * QKV_) return;
    int i = idx / QKV_;
    int j = idx % QKV_;
    float v;
    if (j < 512) {
        int h = j >> 6, o = j & 63;
        v = Wq[(h*D_ + i)*HS_ + o] * 0.125f;               // 1/sqrt(64)
    } else if (j < 1024) {
        int jj = j - 512; int h = jj >> 6, o = jj & 63;
        v = Wk[(h*(D_+E_) + i)*HS_ + o];
    } else {
        int jj = j - 1024; int h = jj >> 6, o = jj & 63;
        v = Wv[(h*D_ + i)*HS_ + o];
    }
    out[idx] = v;
}

// ---------------------------------------------------------------------------
// bf16 hi/lo split: v ~= hi + lo with |err| ~ 2^-18 |v|
// ---------------------------------------------------------------------------
__device__ __forceinline__ void split_bf16(float v, __nv_bfloat16& h, __nv_bfloat16& l)
{
    h = __float2bfloat16(v);
    l = __float2bfloat16(v - __bfloat162float(h));
}

// ---------------------------------------------------------------------------
// Tensor-core GEMM: C[m,n] = sum_k A[m,k]*B[k,n], fp32 I/O, bf16x3 emulation.
//   A: K contiguous, row stride as_m. Batch offsets a_bso/a_bsi (z = bo*inner+bi).
//   B: either bs_n==1 (n contiguous) or bs_k==1 (k contiguous).
//   Optional a_bias (per-k) -> A := relu(A + a_bias)   (FFN2 fuses relu(x@W1+b1))
//   All M,N,K exact multiples of the tile sizes for every call below.
// ---------------------------------------------------------------------------
template<int BM, int BN, int WM, int WN>
__global__ __launch_bounds__(WM*WN*32)
void wgemm(const float* __restrict__ A, const float* __restrict__ Bm,
           const float* __restrict__ a_bias, float* __restrict__ C,
           int K,
           long as_m, long a_bso, long a_bsi,
           long bs_k, long bs_n, long b_bso, long b_bsi,
           long cs_m, long c_bso, long c_bsi,
           int inner)
{
    constexpr int BK  = 32;
    constexpr int NT  = WM*WN*32;
    constexpr int WTM = BM/WM;
    constexpr int WTN = BN/WN;
    constexpr int FM  = WTM/16;
    constexpr int FN  = WTN/16;
    constexpr int LDA = BK + 8;
    constexpr int LDB = BN + 8;

    __shared__ __nv_bfloat16 Ah[BM][LDA], Al[BM][LDA];
    __shared__ __nv_bfloat16 Bh[BK][LDB], Bl[BK][LDB];

    const int t    = threadIdx.x;
    const int warp = t >> 5;
    const int wm   = warp / WN;
    const int wn   = warp % WN;

    const long bo = blockIdx.z / inner;
    const long bi = blockIdx.z % inner;
    const long m0 = (long)blockIdx.y * BM;
    const long n0 = (long)blockIdx.x * BN;

    const float* Ab = A  + bo*a_bso + bi*a_bsi + m0*as_m;
    const float* Bb = Bm + bo*b_bso + bi*b_bsi + n0*bs_n;

    wmma::fragment<wmma::accumulator, 16, 16, 16, float> acc[FM][FN];
#pragma unroll
    for (int i = 0; i < FM; ++i)
#pragma unroll
        for (int j = 0; j < FN; ++j) wmma::fill_fragment(acc[i][j], 0.f);

    for (int k0 = 0; k0 < K; k0 += BK) {
        // ---- A tile (BM x BK), K contiguous in global ----
#pragma unroll
        for (int i = 0; i < (BM*8)/NT; ++i) {
            int f   = t + i*NT;
            int row = f >> 3;
            int c4  = (f & 7) * 4;
            float4 v = *(const float4*)(Ab + (long)row*as_m + k0 + c4);
            if (a_bias) {
                const float4 bb = *(const float4*)(a_bias + k0 + c4);
                v.x = fmaxf(v.x + bb.x, 0.f); v.y = fmaxf(v.y + bb.y, 0.f);
                v.z = fmaxf(v.z + bb.z, 0.f); v.w = fmaxf(v.w + bb.w, 0.f);
            }
            split_bf16(v.x, Ah[row][c4+0], Al[row][c4+0]);
            split_bf16(v.y, Ah[row][c4+1], Al[row][c4+1]);
            split_bf16(v.z, Ah[row][c4+2], Al[row][c4+2]);
            split_bf16(v.w, Ah[row][c4+3], Al[row][c4+3]);
        }
        // ---- B tile (BK x BN) ----
        if (bs_n == 1) {
#pragma unroll
            for (int i = 0; i < (BK*BN/4)/NT; ++i) {
                int f  = t + i*NT;
                int k  = f / (BN/4);
                int n4 = (f % (BN/4)) * 4;
                float4 v = *(const float4*)(Bb + (long)(k0+k)*bs_k + n4);
                split_bf16(v.x, Bh[k][n4+0], Bl[k][n4+0]);
                split_bf16(v.y, Bh[k][n4+1], Bl[k][n4+1]);
                split_bf16(v.z, Bh[k][n4+2], Bl[k][n4+2]);
                split_bf16(v.w, Bh[k][n4+3], Bl[k][n4+3]);
            }
        } else {   // bs_k == 1 (K contiguous in B)
#pragma unroll
            for (int i = 0; i < (BK*BN/4)/NT; ++i) {
                int f  = t + i*NT;
                int n  = f >> 3;
                int c4 = (f & 7) * 4;
                float4 v = *(const float4*)(Bb + (long)n*bs_n + k0 + c4);
                split_bf16(v.x, Bh[c4+0][n], Bl[c4+0][n]);
                split_bf16(v.y, Bh[c4+1][n], Bl[c4+1][n]);
                split_bf16(v.z, Bh[c4+2][n], Bl[c4+2][n]);
                split_bf16(v.w, Bh[c4+3][n], Bl[c4+3][n]);
            }
        }
        __syncthreads();

#pragma unroll
        for (int kk = 0; kk < BK/16; ++kk) {
            wmma::fragment<wmma::matrix_a, 16, 16, 16, __nv_bfloat16, wmma::row_major> ah[FM], al[FM];
#pragma unroll
            for (int fm = 0; fm < FM; ++fm) {
                wmma::load_matrix_sync(ah[fm], &Ah[wm*WTM + fm*16][kk*16], LDA);
                wmma::load_matrix_sync(al[fm], &Al[wm*WTM + fm*16][kk*16], LDA);
            }
#pragma unroll
            for (int fn = 0; fn < FN; ++fn) {
                wmma::fragment<wmma::matrix_b, 16, 16, 16, __nv_bfloat16, wmma::row_major> bh, bl;
                wmma::load_matrix_sync(bh, &Bh[kk*16][wn*WTN + fn*16], LDB);
                wmma::load_matrix_sync(bl, &Bl[kk*16][wn*WTN + fn*16], LDB);
#pragma unroll
                for (int fm = 0; fm < FM; ++fm) {
                    wmma::mma_sync(acc[fm][fn], ah[fm], bh, acc[fm][fn]);
                    wmma::mma_sync(acc[fm][fn], ah[fm], bl, acc[fm][fn]);
                    wmma::mma_sync(acc[fm][fn], al[fm], bh, acc[fm][fn]);
                }
            }
        }
        __syncthreads();
    }

    float* Cb = C + bo*c_bso + bi*c_bsi;
#pragma unroll
    for (int fm = 0; fm < FM; ++fm)
#pragma unroll
        for (int fn = 0; fn < FN; ++fn)
            wmma::store_matrix_sync(Cb + (m0 + wm*WTM + fm*16)*cs_m + n0 + wn*WTN + fn*16,
                                    acc[fm][fn], cs_m, wmma::mem_row_major);
}

// ---------------------------------------------------------------------------
// Edge-conditioned logits + softmax, fused. One CTA per (b, n).
//   logits[b,h,n,m] += sum_e qe[b,n,h,e] * edge[b,n,m,e]  ; softmax over m.
// Streams 536 MB of edge exactly once (DRAM-bound). 128 threads.
// ---------------------------------------------------------------------------
#define EDGE_SMEM_BYTES ((8192 + 256*17*4 + 128*4) * 4)   // 104448

__global__ __launch_bounds__(128)
void edge_softmax_kernel(const float* __restrict__ edge,
                         const float* __restrict__ qe,
                         float* __restrict__ logits)
{
    extern __shared__ float smem[];
    float*  s_logits = smem;                       // 8192 floats
    float4* s_edge4  = (float4*)(smem + 8192);     // 256*17 float4
    float4* s_qe4    = s_edge4 + 256*17;           // 128 float4

    const int t  = threadIdx.x;
    const int bn = blockIdx.x;
    const int b  = bn >> 10;
    const int n  = bn & 1023;

    s_qe4[t] = ((const float4*)(qe + (long)bn*512))[t];

    const float* lg = logits + ((long)(b*H_)*N_ + n) * N_;
#pragma unroll
    for (int h = 0; h < H_; ++h) {
        const float4* src = (const float4*)(lg + (long)h*N_*N_);
        float4* dst = (float4*)(s_logits + h*N_);
        dst[t]       = src[t];
        dst[t + 128] = src[t + 128];
    }
    __syncthreads();

    const float4* eg = (const float4*)(edge + ((long)bn << 16));
    const int tx = t & 63;            // m lane
    const int hy = (t >> 6) << 2;     // head group base: 0 or 4

    for (int mt = 0; mt < 4; ++mt) {
#pragma unroll 8
        for (int i = 0; i < 32; ++i) {
            int f   = t + i*128;
            int row = f >> 4, c = f & 15;
            s_edge4[row*17 + c] = eg[(mt*256 + row)*16 + c];
        }
        __syncthreads();

        float acc[4][4];
#pragma unroll
        for (int i = 0; i < 4; ++i)
#pragma unroll
            for (int j = 0; j < 4; ++j) acc[i][j] = 0.f;

#pragma unroll
        for (int e4 = 0; e4 < 16; ++e4) {
            float4 ev[4], qv[4];
#pragma unroll
            for (int i = 0; i < 4; ++i) ev[i] = s_edge4[(tx + i*64)*17 + e4];
#pragma unroll
            for (int j = 0; j < 4; ++j) qv[j] = s_qe4[(hy + j)*16 + e4];
#pragma unroll
            for (int i = 0; i < 4; ++i)
#pragma unroll
                for (int j = 0; j < 4; ++j)
                    acc[i][j] += ev[i].x*qv[j].x + ev[i].y*qv[j].y
                               + ev[i].z*qv[j].z + ev[i].w*qv[j].w;
        }
#pragma unroll
        for (int j = 0; j < 4; ++j)
#pragma unroll
            for (int i = 0; i < 4; ++i)
                s_logits[(hy + j)*N_ + mt*256 + i*64 + tx] += acc[i][j];
        __syncthreads();
    }

    const int warp = t >> 5, lane = t & 31;
    for (int h = warp; h < H_; h += 4) {
        const float* row = s_logits + h*N_;
        float mx = -1e30f;
#pragma unroll
        for (int i = 0; i < 32; ++i) mx = fmaxf(mx, row[lane + i*32]);
#pragma unroll
        for (int o = 16; o; o >>= 1) mx = fmaxf(mx, __shfl_xor_sync(~0u, mx, o));
        float vals[32];
        float sum = 0.f;
#pragma unroll
        for (int i = 0; i < 32; ++i) {
            vals[i] = __expf(row[lane + i*32] - mx);
            sum += vals[i];
        }
#pragma unroll
        for (int o = 16; o; o >>= 1) sum += __shfl_xor_sync(~0u, sum, o);
        const float inv = 1.f / sum;
        float* out = logits + ((long)(b*H_ + h)*N_ + n) * N_;
#pragma unroll
        for (int i = 0; i < 32; ++i) out[lane + i*32] = vals[i] * inv;
    }
}

// ---------------------------------------------------------------------------
// LayerNorm over last dim (256), fused residual + residual-bias.
// out = LN(a + r + rb) * g + beta.  Warp per row.
// ---------------------------------------------------------------------------
__global__ __launch_bounds__(256)
void ln_kernel(const float* __restrict__ a, const float* __restrict__ r,
               const float* __restrict__ rb,
               const float* __restrict__ gam, const float* __restrict__ bet,
               float* __restrict__ out)
{
    const int warp = threadIdx.x >> 5, lane = threadIdx.x & 31;
    const long row = (long)blockIdx.x * 8 + warp;
    const float4* pa = (const float4*)(a + row*D_);
    const float4* pr = (const float4*)(r + row*D_);
    const float4 rb0 = ((const float4*)rb)[lane], rb1 = ((const float4*)rb)[lane + 32];
    float4 v0 = pa[lane], v1 = pa[lane + 32];
    const float4 q0 = pr[lane], q1 = pr[lane + 32];
    v0.x += q0.x + rb0.x; v0.y += q0.y + rb0.y; v0.z += q0.z + rb0.z; v0.w += q0.w + rb0.w;
    v1.x += q1.x + rb1.x; v1.y += q1.y + rb1.y; v1.z += q1.z + rb1.z; v1.w += q1.w + rb1.w;

    float s = v0.x + v0.y + v0.z + v0.w + v1.x + v1.y + v1.z + v1.w;
#pragma unroll
    for (int o = 16; o; o >>= 1) s += __shfl_xor_sync(~0u, s, o);
    const float mu = s * (1.f / 256.f);

    float4 d0, d1;
    d0.x = v0.x - mu; d0.y = v0.y - mu; d0.z = v0.z - mu; d0.w = v0.w - mu;
    d1.x = v1.x - mu; d1.y = v1.y - mu; d1.z = v1.z - mu; d1.w = v1.w - mu;
    float var = d0.x*d0.x + d0.y*d0.y + d0.z*d0.z + d0.w*d0.w
              + d1.x*d1.x + d1.y*d1.y + d1.z*d1.z + d1.w*d1.w;
#pragma unroll
    for (int o = 16; o; o >>= 1) var += __shfl_xor_sync(~0u, var, o);
    const float rs = rsqrtf(var * (1.f / 256.f) + 1e-6f);

    const float4 g0 = ((const float4*)gam)[lane], g1 = ((const float4*)gam)[lane + 32];
    const float4 b0 = ((const float4*)bet)[lane], b1 = ((const float4*)bet)[lane + 32];
    float4 o0, o1;
    o0.x = d0.x*rs*g0.x + b0.x; o0.y = d0.y*rs*g0.y + b0.y;
    o0.z = d0.z*rs*g0.z + b0.z; o0.w = d0.w*rs*g0.w + b0.w;
    o1.x = d1.x*rs*g1.x + b1.x; o1.y = d1.y*rs*g1.y + b1.y;
    o1.z = d1.z*rs*g1.z + b1.z; o1.w = d1.w*rs*g1.w + b1.w;
    ((float4*)(out + row*D_))[lane]      = o0;
    ((float4*)(out + row*D_))[lane + 32] = o1;
}

// ---------------------------------------------------------------------------
// Host launch (graph-capturable)
// ---------------------------------------------------------------------------
extern "C" void kernel_launch(void* const* d_in, const int* in_sizes, int n_in,
                              void* d_out, int out_size)
{
    const float* node = (const float*)d_in[0];
    const float* edge = (const float*)d_in[1];
    const float* Wq   = (const float*)d_in[2];
    const float* Wk   = (const float*)d_in[3];
    const float* Wv   = (const float*)d_in[4];
    const float* Wp   = (const float*)d_in[5];
    const float* bp   = (const float*)d_in[6];
    const float* ln1g = (const float*)d_in[7];
    const float* ln1b = (const float*)d_in[8];
    const float* W1   = (const float*)d_in[9];
    const float* b1   = (const float*)d_in[10];
    const float* W2   = (const float*)d_in[11];
    const float* b2   = (const float*)d_in[12];
    const float* ln2g = (const float*)d_in[13];
    const float* ln2b = (const float*)d_in[14];

    float *qkv, *qe, *logits, *mo, *mha, *x, *ffh, *ff, *wqkv;
    cudaGetSymbolAddress((void**)&qkv,    g_qkv);
    cudaGetSymbolAddress((void**)&qe,     g_qe);
    cudaGetSymbolAddress((void**)&logits, g_logits);
    cudaGetSymbolAddress((void**)&mo,     g_mo);
    cudaGetSymbolAddress((void**)&mha,    g_mha);
    cudaGetSymbolAddress((void**)&x,      g_x);
    cudaGetSymbolAddress((void**)&ffh,    g_ffh);
    cudaGetSymbolAddress((void**)&ff,     g_ff);
    cudaGetSymbolAddress((void**)&wqkv,   g_wqkv);

    cudaFuncSetAttribute(edge_softmax_kernel,
                         cudaFuncAttributeMaxDynamicSharedMemorySize,
                         EDGE_SMEM_BYTES);

    // 0) weight repack
    repack_wqkv<<<(D_*QKV_ + 255)/256, 256>>>(Wq, Wk, Wv, wqkv);

    // 1) fused QKV projection: [2048,1536] = node @ wqkv
    wgemm<128,64,4,2><<<dim3(QKV_/64, R_/128, 1), 256>>>(
        node, wqkv, nullptr, qkv, D_,
        D_, 0, 0,
        QKV_, 1, 0, 0,
        QKV_, 0, 0, 1);

    // 2) qe[r, h*64+e] = q_h[r,:] @ WkE_h^T  (batch over h)
    wgemm<128,64,4,2><<<dim3(1, R_/128, H_), 256>>>(
        qkv, Wk + (long)D_*HS_, nullptr, qe, HS_,
        QKV_, 64, 0,
        1, HS_, (long)(D_+E_)*HS_, 0,
        (long)H_*E_, 64, 0, 1);

    // 3) QK^T logits: batch over (b,h)
    wgemm<128,64,4,2><<<dim3(N_/64, N_/128, B_*H_), 256>>>(
        qkv, qkv + 512, nullptr, logits, HS_,
        QKV_, (long)N_*QKV_, 64,
        1, QKV_, (long)N_*QKV_, 64,
        N_, (long)H_*N_*N_, (long)N_*N_, H_);

    // 4) edge logits + softmax (streams 536 MB; in-place probs)
    edge_softmax_kernel<<<R_, 128, EDGE_SMEM_BYTES>>>(edge, qe, logits);

    // 5) AV: mo[b,n,h,:] = attn[b,h,n,:] @ v[b,:,h,:]
    wgemm<128,64,4,2><<<dim3(1, N_/128, B_*H_), 256>>>(
        logits, qkv + 1024, nullptr, mo, N_,
        N_, (long)H_*N_*N_, (long)N_*N_,
        QKV_, 1, (long)N_*QKV_, 64,
        (long)H_*HS_, (long)N_*H_*HS_, 64, H_);

    // 6) output projection: mha = mo @ Wp  (bias bp folded into LN1)
    wgemm<64,64,2,2><<<dim3(D_/64, R_/64, 1), 128>>>(
        mo, Wp, nullptr, mha, H_*HS_,
        (long)H_*HS_, 0, 0,
        D_, 1, 0, 0,
        D_, 0, 0, 1);

    // 7) x = LN1(node + mha + bp)
    ln_kernel<<<R_/8, 256>>>(node, mha, bp, ln1g, ln1b, x);

    // 8) FFN hidden (raw): ffh = x @ W1   (b1+relu fused into step 9's A load)
    wgemm<128,64,4,2><<<dim3(FF_/64, R_/128, 1), 256>>>(
        x, W1, nullptr, ffh, D_,
        D_, 0, 0,
        FF_, 1, 0, 0,
        FF_, 0, 0, 1);

    // 9) FFN out (raw): ff = relu(ffh + b1) @ W2   (b2 folded into LN2)
    wgemm<64,64,2,2><<<dim3(D_/64, R_/64, 1), 128>>>(
        ffh, W2, b1, ff, FF_,
        FF_, 0, 0,
        D_, 1, 0, 0,
        D_, 0, 0, 1);

    // 10) out = LN2(x + ff + b2)
    ln_kernel<<<R_/8, 256>>>(x, ff, b2, ln2g, ln2b, (float*)d_out);
}